// round 3
// baseline (speedup 1.0000x reference)
#include <cuda_runtime.h>
#include <cstdint>

#define N_NODES 50000
#define N_EDGES 1600000
#define F 48
#define NREL 8

// nodes per block for transform
#define NT 64
#define NTP (NT + 4)   // padded row to avoid smem bank conflicts
#define TPB1 192
#define EPB 16         // edges per block in edge kernel (16*12 = 192 threads)
#define TPB2 192

typedef unsigned long long u64;

// Per-(node,rel) transformed messages: 50000*8*48 floats = 76.8 MB (static device scratch)
__device__ float g_h2[(size_t)N_NODES * NREL * F];

// packed fp32x2 FMA: 2 MACs per fma-pipe slot (FFMA2)
__device__ __forceinline__ u64 fma2(u64 a, u64 b, u64 c) {
    u64 d;
    asm("fma.rn.f32x2 %0, %1, %2, %3;" : "=l"(d) : "l"(a), "l"(b), "l"(c));
    return d;
}
__device__ __forceinline__ float2 unpk(u64 v) {
    float2 f;
    asm("mov.b64 {%0, %1}, %2;" : "=f"(f.x), "=f"(f.y) : "l"(v));
    return f;
}

// ---------------------------------------------------------------------------
// Kernel 1: h2[n,r,:] = relu(x[n] @ W1[r] + b1) @ W2[r]
// Thread tile: 2 node-pairs x 4 cols, inner loop = 8 FFMA2 (16 MACs) +
// 1 LDS.128 (x node-pairs) + 2 LDS.128 (duplicated W pairs).
// sWd holds the current-phase weight matrix with each element duplicated
// (w,w) so the FFMA2 B-operand is a plain 64-bit shared load.
// ---------------------------------------------------------------------------
__global__ __launch_bounds__(TPB1) void transform_kernel(
    const float* __restrict__ x, const float* __restrict__ W1,
    const float* __restrict__ W2, const float* __restrict__ b1)
{
    __shared__ __align__(16) float sWd[F][F * 2];   // duplicated weights (phase 1: W1, phase 2: W2)
    __shared__ __align__(16) float sT[F][NTP];      // xT, then h1T

    const int r   = blockIdx.y;
    const int n0  = blockIdx.x * NT;
    const int tid = threadIdx.x;
    const int cg  = tid % 12;  // 12 col groups * 4 cols = 48
    const int ng  = tid / 12;  // 16 node groups * 4 nodes = 64

    // stage W1, duplicated per element
    for (int i = tid; i < F * F; i += TPB1) {
        float w = W1[(size_t)r * F * F + i];
        int row = i / F, col = i % F;
        sWd[row][col * 2]     = w;
        sWd[row][col * 2 + 1] = w;
    }
    // stage x, transposed: sT[i][n]
    for (int idx = tid; idx < NT * F; idx += TPB1) {
        int n = idx / F, i = idx % F;
        int gn = n0 + n;
        sT[i][n] = (gn < N_NODES) ? x[(size_t)gn * F + i] : 0.f;
    }
    __syncthreads();

    u64 acc[2][4];

    // -------- phase 1: h1 = relu(x @ W1 + b1) --------
    #pragma unroll
    for (int p = 0; p < 2; p++)
        #pragma unroll
        for (int c = 0; c < 4; c++) acc[p][c] = 0ull;

    #pragma unroll 8
    for (int i = 0; i < F; i++) {
        const u64* xp = reinterpret_cast<const u64*>(&sT[i][ng * 4]);
        u64 x0 = xp[0], x1 = xp[1];
        const u64* wd = reinterpret_cast<const u64*>(&sWd[i][cg * 8]);
        u64 w0 = wd[0], w1 = wd[1], w2 = wd[2], w3 = wd[3];
        acc[0][0] = fma2(x0, w0, acc[0][0]);
        acc[0][1] = fma2(x0, w1, acc[0][1]);
        acc[0][2] = fma2(x0, w2, acc[0][2]);
        acc[0][3] = fma2(x0, w3, acc[0][3]);
        acc[1][0] = fma2(x1, w0, acc[1][0]);
        acc[1][1] = fma2(x1, w1, acc[1][1]);
        acc[1][2] = fma2(x1, w2, acc[1][2]);
        acc[1][3] = fma2(x1, w3, acc[1][3]);
    }

    // everyone finished READING sT/sWd (phase-1 operands live in acc regs now)
    __syncthreads();

    // epilogue: bias + relu, write h1 transposed back into sT
    {
        float4 bv = *reinterpret_cast<const float4*>(&b1[cg * 4]);
        float ba[4] = {bv.x, bv.y, bv.z, bv.w};
        #pragma unroll
        for (int c = 0; c < 4; c++) {
            float2 a0 = unpk(acc[0][c]);
            float2 a1 = unpk(acc[1][c]);
            float4 hv;
            hv.x = fmaxf(a0.x + ba[c], 0.f);
            hv.y = fmaxf(a0.y + ba[c], 0.f);
            hv.z = fmaxf(a1.x + ba[c], 0.f);
            hv.w = fmaxf(a1.y + ba[c], 0.f);
            *reinterpret_cast<float4*>(&sT[cg * 4 + c][ng * 4]) = hv;
        }
    }
    // restage W2 (duplicated) into sWd
    for (int i = tid; i < F * F; i += TPB1) {
        float w = W2[(size_t)r * F * F + i];
        int row = i / F, col = i % F;
        sWd[row][col * 2]     = w;
        sWd[row][col * 2 + 1] = w;
    }
    __syncthreads();

    // -------- phase 2: h2 = h1 @ W2 --------
    #pragma unroll
    for (int p = 0; p < 2; p++)
        #pragma unroll
        for (int c = 0; c < 4; c++) acc[p][c] = 0ull;

    #pragma unroll 8
    for (int j = 0; j < F; j++) {
        const u64* hp = reinterpret_cast<const u64*>(&sT[j][ng * 4]);
        u64 h0 = hp[0], h1v = hp[1];
        const u64* wd = reinterpret_cast<const u64*>(&sWd[j][cg * 8]);
        u64 w0 = wd[0], w1 = wd[1], w2 = wd[2], w3 = wd[3];
        acc[0][0] = fma2(h0, w0, acc[0][0]);
        acc[0][1] = fma2(h0, w1, acc[0][1]);
        acc[0][2] = fma2(h0, w2, acc[0][2]);
        acc[0][3] = fma2(h0, w3, acc[0][3]);
        acc[1][0] = fma2(h1v, w0, acc[1][0]);
        acc[1][1] = fma2(h1v, w1, acc[1][1]);
        acc[1][2] = fma2(h1v, w2, acc[1][2]);
        acc[1][3] = fma2(h1v, w3, acc[1][3]);
    }

    // unpack and store h2
    float m[4][4];
    #pragma unroll
    for (int c = 0; c < 4; c++) {
        float2 a0 = unpk(acc[0][c]);
        float2 a1 = unpk(acc[1][c]);
        m[0][c] = a0.x; m[1][c] = a0.y; m[2][c] = a1.x; m[3][c] = a1.y;
    }
    #pragma unroll
    for (int u = 0; u < 4; u++) {
        int gn = n0 + ng * 4 + u;
        if (gn < N_NODES) {
            *reinterpret_cast<float4*>(&g_h2[((size_t)gn * NREL + r) * F + cg * 4]) =
                make_float4(m[u][0], m[u][1], m[u][2], m[u][3]);
        }
    }
}

// ---------------------------------------------------------------------------
// Kernel 2: per-edge gather h2[src,rel] * norm, scatter-add into out[dst]
// Thread -> (edge, float4-slot): 12 consecutive lanes cover one edge's 192B
// row (coalesced gather + vector RED).
// ---------------------------------------------------------------------------
__global__ __launch_bounds__(TPB2) void edge_kernel(
    const int* __restrict__ src, const int* __restrict__ dst,
    const int* __restrict__ rel, const float* __restrict__ norm,
    float* __restrict__ out)
{
    const int tid = threadIdx.x;
    const int e = blockIdx.x * EPB + tid / 12;
    const int k = tid % 12;
    if (e >= N_EDGES) return;

    int s = __ldg(src + e);
    int d = __ldg(dst + e);
    int r = __ldg(rel + e);
    float w = __ldg(norm + e);

    float4 v = *reinterpret_cast<const float4*>(
        &g_h2[((size_t)s * NREL + r) * F + k * 4]);

    float* o = out + (size_t)d * F + k * 4;
    asm volatile("red.global.add.v4.f32 [%0], {%1, %2, %3, %4};"
                 :: "l"(o),
                    "f"(v.x * w), "f"(v.y * w), "f"(v.z * w), "f"(v.w * w)
                 : "memory");
}

// ---------------------------------------------------------------------------
// Kernel 3: out = relu(agg + bias2)
// ---------------------------------------------------------------------------
__global__ void finalize_kernel(float* __restrict__ out, const float* __restrict__ b2)
{
    int i = blockIdx.x * blockDim.x + threadIdx.x;
    if (i < N_NODES * F) {
        float v = out[i] + b2[i % F];
        out[i] = fmaxf(v, 0.f);
    }
}

// ---------------------------------------------------------------------------
extern "C" void kernel_launch(void* const* d_in, const int* in_sizes, int n_in,
                              void* d_out, int out_size)
{
    const float* x    = (const float*)d_in[0];
    const float* norm = (const float*)d_in[1];
    const float* W1   = (const float*)d_in[2];
    const float* W2   = (const float*)d_in[3];
    const float* b1   = (const float*)d_in[4];
    const float* b2   = (const float*)d_in[5];
    const int*   src  = (const int*)d_in[6];
    const int*   dst  = (const int*)d_in[7];
    const int*   rel  = (const int*)d_in[8];
    float* out = (float*)d_out;

    // output accumulates atomics; must be zeroed every replay
    cudaMemsetAsync(out, 0, (size_t)N_NODES * F * sizeof(float), 0);

    dim3 g1((N_NODES + NT - 1) / NT, NREL);
    transform_kernel<<<g1, TPB1>>>(x, W1, W2, b1);

    edge_kernel<<<(N_EDGES + EPB - 1) / EPB, TPB2>>>(src, dst, rel, norm, out);

    finalize_kernel<<<(N_NODES * F + 255) / 256, 256>>>(out, b2);
}

// round 4
// speedup vs baseline: 1.5793x; 1.5793x over previous
#include <cuda_runtime.h>
#include <cstdint>

#define N_NODES 50000
#define N_EDGES 1600000
#define F 48
#define NREL 8

// transform tiling
#define NT 64
#define NTP (NT + 4)
#define TPB1 192

// scan config
#define SCB 1024
#define SB ((N_NODES + SCB - 1) / SCB)   // 49 blocks

// agg config
#define GPD 16                            // dst nodes per block (16*12 = 192 thr)
#define TPBA 192

typedef unsigned long long u64;

// ------------------------- static device scratch ---------------------------
__device__ float g_h2[(size_t)N_NODES * NREL * F];   // 76.8 MB
__device__ int   g_counts[N_NODES];
__device__ int   g_offsets[N_NODES + 1];
__device__ int   g_cursors[N_NODES];
__device__ u64   g_recs[N_EDGES];                    // {norm:f32 hi, srel:u32 lo}
__device__ int   g_blocksums[SB];

// ---------------------------------------------------------------------------
// Kernel 1: h2[n,r,:] = relu(x[n] @ W1[r] + b1) @ W2[r]   (round-2 version)
// ---------------------------------------------------------------------------
__global__ __launch_bounds__(TPB1) void transform_kernel(
    const float* __restrict__ x, const float* __restrict__ W1,
    const float* __restrict__ W2, const float* __restrict__ b1)
{
    __shared__ __align__(16) float sW1[F * F];
    __shared__ __align__(16) float sW2[F * F];
    __shared__ __align__(16) float sT[F][NTP];   // xT, then h1T

    const int r   = blockIdx.y;
    const int n0  = blockIdx.x * NT;
    const int tid = threadIdx.x;
    const int cg  = tid % 12;
    const int ng  = tid / 12;

    for (int i = tid; i < F * F; i += TPB1) {
        sW1[i] = W1[(size_t)r * F * F + i];
        sW2[i] = W2[(size_t)r * F * F + i];
    }
    for (int idx = tid; idx < NT * F; idx += TPB1) {
        int n = idx / F, i = idx % F;
        int gn = n0 + n;
        sT[i][n] = (gn < N_NODES) ? x[(size_t)gn * F + i] : 0.f;
    }
    __syncthreads();

    float acc[4][4];

    #pragma unroll
    for (int u = 0; u < 4; u++)
        #pragma unroll
        for (int c = 0; c < 4; c++) acc[u][c] = 0.f;

    #pragma unroll 8
    for (int i = 0; i < F; i++) {
        float4 xv = *reinterpret_cast<const float4*>(&sT[i][ng * 4]);
        float4 wv = *reinterpret_cast<const float4*>(&sW1[i * F + cg * 4]);
        float xa[4] = {xv.x, xv.y, xv.z, xv.w};
        float wa[4] = {wv.x, wv.y, wv.z, wv.w};
        #pragma unroll
        for (int u = 0; u < 4; u++)
            #pragma unroll
            for (int c = 0; c < 4; c++)
                acc[u][c] += xa[u] * wa[c];
    }
    __syncthreads();   // done reading sT

    {
        float4 bv = *reinterpret_cast<const float4*>(&b1[cg * 4]);
        float ba[4] = {bv.x, bv.y, bv.z, bv.w};
        #pragma unroll
        for (int c = 0; c < 4; c++) {
            float4 hv;
            hv.x = fmaxf(acc[0][c] + ba[c], 0.f);
            hv.y = fmaxf(acc[1][c] + ba[c], 0.f);
            hv.z = fmaxf(acc[2][c] + ba[c], 0.f);
            hv.w = fmaxf(acc[3][c] + ba[c], 0.f);
            *reinterpret_cast<float4*>(&sT[cg * 4 + c][ng * 4]) = hv;
        }
    }
    __syncthreads();

    #pragma unroll
    for (int u = 0; u < 4; u++)
        #pragma unroll
        for (int c = 0; c < 4; c++) acc[u][c] = 0.f;

    #pragma unroll 8
    for (int j = 0; j < F; j++) {
        float4 hv = *reinterpret_cast<const float4*>(&sT[j][ng * 4]);
        float4 wv = *reinterpret_cast<const float4*>(&sW2[j * F + cg * 4]);
        float ha[4] = {hv.x, hv.y, hv.z, hv.w};
        float wa[4] = {wv.x, wv.y, wv.z, wv.w};
        #pragma unroll
        for (int u = 0; u < 4; u++)
            #pragma unroll
            for (int c = 0; c < 4; c++)
                acc[u][c] += ha[u] * wa[c];
    }

    #pragma unroll
    for (int u = 0; u < 4; u++) {
        int gn = n0 + ng * 4 + u;
        if (gn < N_NODES) {
            *reinterpret_cast<float4*>(&g_h2[((size_t)gn * NREL + r) * F + cg * 4]) =
                make_float4(acc[u][0], acc[u][1], acc[u][2], acc[u][3]);
        }
    }
}

// ---------------------------------------------------------------------------
// CSR build: histogram -> scan -> scatter packed records
// ---------------------------------------------------------------------------
__global__ void hist_kernel(const int* __restrict__ dst)
{
    int e = blockIdx.x * blockDim.x + threadIdx.x;
    if (e < N_EDGES) atomicAdd(&g_counts[dst[e]], 1);
}

// per-block exclusive scan of counts -> offsets (local), block totals out
__global__ __launch_bounds__(SCB) void scan1_kernel()
{
    __shared__ int s[SCB];
    int tid = threadIdx.x;
    int i = blockIdx.x * SCB + tid;
    int v = (i < N_NODES) ? g_counts[i] : 0;
    s[tid] = v;
    __syncthreads();
    #pragma unroll
    for (int off = 1; off < SCB; off <<= 1) {
        int t = (tid >= off) ? s[tid - off] : 0;
        __syncthreads();
        s[tid] += t;
        __syncthreads();
    }
    if (i < N_NODES) g_offsets[i] = s[tid] - v;     // local exclusive
    if (tid == SCB - 1) g_blocksums[blockIdx.x] = s[tid];
}

__global__ void scan2_kernel()
{
    if (threadIdx.x == 0) {
        int run = 0;
        #pragma unroll
        for (int b = 0; b < SB; b++) {
            int t = g_blocksums[b];
            g_blocksums[b] = run;
            run += t;
        }
        g_offsets[N_NODES] = run;   // == N_EDGES
    }
}

__global__ __launch_bounds__(SCB) void scan3_kernel()
{
    int i = blockIdx.x * SCB + threadIdx.x;
    if (i < N_NODES) {
        int o = g_offsets[i] + g_blocksums[blockIdx.x];
        g_offsets[i] = o;
        g_cursors[i] = o;
    }
}

__global__ void scatter_kernel(
    const int* __restrict__ src, const int* __restrict__ dst,
    const int* __restrict__ rel, const float* __restrict__ norm)
{
    int e = blockIdx.x * blockDim.x + threadIdx.x;
    if (e >= N_EDGES) return;
    int d = dst[e];
    int pos = atomicAdd(&g_cursors[d], 1);
    uint32_t srel = (uint32_t)src[e] * NREL + (uint32_t)rel[e];
    uint32_t wb = __float_as_uint(norm[e]);
    g_recs[pos] = ((u64)wb << 32) | (u64)srel;
}

// ---------------------------------------------------------------------------
// Aggregation: 12 lanes per dst node accumulate all incoming messages in
// registers, then fused bias2+relu store. No atomics, no output memset.
// ---------------------------------------------------------------------------
__global__ __launch_bounds__(TPBA) void agg_kernel(
    const float* __restrict__ b2, float* __restrict__ out)
{
    const int tid = threadIdx.x;
    const int g = blockIdx.x * GPD + tid / 12;
    const int k = tid % 12;
    if (g >= N_NODES) return;

    const int start = g_offsets[g];
    const int end   = g_offsets[g + 1];

    float4 acc = make_float4(0.f, 0.f, 0.f, 0.f);

    u64 rec = (start < end) ? g_recs[start] : 0ull;
    for (int e = start; e < end; e++) {
        u64 next = (e + 1 < end) ? g_recs[e + 1] : 0ull;   // prefetch: breaks chain
        uint32_t srel = (uint32_t)rec;
        float w = __uint_as_float((uint32_t)(rec >> 32));
        float4 v = *reinterpret_cast<const float4*>(&g_h2[(size_t)srel * F + k * 4]);
        acc.x += v.x * w;
        acc.y += v.y * w;
        acc.z += v.z * w;
        acc.w += v.w * w;
        rec = next;
    }

    float4 bv = reinterpret_cast<const float4*>(b2)[k];
    float4 o;
    o.x = fmaxf(acc.x + bv.x, 0.f);
    o.y = fmaxf(acc.y + bv.y, 0.f);
    o.z = fmaxf(acc.z + bv.z, 0.f);
    o.w = fmaxf(acc.w + bv.w, 0.f);
    *reinterpret_cast<float4*>(&out[(size_t)g * F + k * 4]) = o;
}

// ---------------------------------------------------------------------------
extern "C" void kernel_launch(void* const* d_in, const int* in_sizes, int n_in,
                              void* d_out, int out_size)
{
    const float* x    = (const float*)d_in[0];
    const float* norm = (const float*)d_in[1];
    const float* W1   = (const float*)d_in[2];
    const float* W2   = (const float*)d_in[3];
    const float* b1   = (const float*)d_in[4];
    const float* b2   = (const float*)d_in[5];
    const int*   src  = (const int*)d_in[6];
    const int*   dst  = (const int*)d_in[7];
    const int*   rel  = (const int*)d_in[8];
    float* out = (float*)d_out;

    void* counts_ptr = nullptr;
    cudaGetSymbolAddress(&counts_ptr, g_counts);
    cudaMemsetAsync(counts_ptr, 0, N_NODES * sizeof(int), 0);

    // CSR build (independent of transform)
    hist_kernel<<<(N_EDGES + 255) / 256, 256>>>(dst);
    scan1_kernel<<<SB, SCB>>>();
    scan2_kernel<<<1, 32>>>();
    scan3_kernel<<<SB, SCB>>>();
    scatter_kernel<<<(N_EDGES + 255) / 256, 256>>>(src, dst, rel, norm);

    // per-(node,rel) transform
    dim3 g1((N_NODES + NT - 1) / NT, NREL);
    transform_kernel<<<g1, TPB1>>>(x, W1, W2, b1);

    // gather + reduce + bias + relu
    agg_kernel<<<(N_NODES + GPD - 1) / GPD, TPBA>>>(b2, out);
}